// round 3
// baseline (speedup 1.0000x reference)
#include <cuda_runtime.h>
#include <cuda_bf16.h>

namespace {

struct P {
  const float *feat0, *feat1, *edge_inv;
  const int *src, *dst;
  const float *b00, *b01, *b10, *b11;
  const float *w1a, *b1a, *w2a, *b2a, *w3a;   // pair A of the kernel
  const float *w1b, *b1b, *w2b, *b2b, *w3b;   // pair B of the kernel
  float* out;
  int E;
};

__device__ __forceinline__ void cpcopy(float* d, const float* __restrict__ s, int n) {
  for (int i = threadIdx.x; i < n; i += blockDim.x) d[i] = s[i];
}

// h2 = relu(relu(ei@w1+b1)@w2+b2). mlp smem layout: w1[64]|b1[32]|w2[1024]|b2[32]
__device__ __forceinline__ void radial(const float* __restrict__ mlp, float* h1s,
                                       float ei0, float ei1, float h2[32]) {
  const float* w1 = mlp; const float* b1 = mlp + 64;
  const float* w2 = mlp + 96; const float* b2 = mlp + 1120;
#pragma unroll
  for (int m = 0; m < 32; m++)
    h1s[m] = fmaxf(fmaf(ei0, w1[m], fmaf(ei1, w1[32 + m], b1[m])), 0.f);
#pragma unroll
  for (int mb = 0; mb < 8; mb++) {
    float a0 = b2[mb*4], a1 = b2[mb*4+1], a2 = b2[mb*4+2], a3 = b2[mb*4+3];
#pragma unroll 4
    for (int n = 0; n < 32; n++) {
      float h = h1s[n];
      float4 w = *reinterpret_cast<const float4*>(w2 + n*32 + mb*4);
      a0 = fmaf(h, w.x, a0); a1 = fmaf(h, w.y, a1);
      a2 = fmaf(h, w.z, a2); a3 = fmaf(h, w.w, a3);
    }
    h2[mb*4]   = fmaxf(a0, 0.f); h2[mb*4+1] = fmaxf(a1, 0.f);
    h2[mb*4+2] = fmaxf(a2, 0.f); h2[mb*4+3] = fmaxf(a3, 0.f);
  }
}

// ---------- kernel A: pairs (0,0)+(1,0) -> out[..,c,0] ----------
// smem: w3_00[8192] | w3_10[8192] | mlp00[1152] | mlp10[1152] | h1[256*33]
constexpr int A_W00 = 0, A_W10 = 8192, A_M00 = 16384, A_M10 = 17536, A_H1 = 18688;
constexpr int A_FLOATS = A_H1 + 256*33;   // 27136 f = 108544 B

__global__ void __launch_bounds__(256, 2) convA(P p) {
  extern __shared__ float sm[];
  cpcopy(sm + A_W00, p.w3a, 8192);
  cpcopy(sm + A_W10, p.w3b, 8192);
  cpcopy(sm + A_M00, p.w1a, 64);  cpcopy(sm + A_M00+64,  p.b1a, 32);
  cpcopy(sm + A_M00+96, p.w2a, 1024); cpcopy(sm + A_M00+1120, p.b2a, 32);
  cpcopy(sm + A_M10, p.w1b, 64);  cpcopy(sm + A_M10+64,  p.b1b, 32);
  cpcopy(sm + A_M10+96, p.w2b, 1024); cpcopy(sm + A_M10+1120, p.b2b, 32);
  __syncthreads();

  int e = blockIdx.x * 256 + threadIdx.x;
  if (e >= p.E) return;
  float* h1p = sm + A_H1 + threadIdx.x * 33;

  int s = p.src[e], d = p.dst[e];
  float ei0 = p.edge_inv[2*e], ei1 = p.edge_inv[2*e+1];
  float h2a[32], h2b[32];
  radial(sm + A_M00, h1p, ei0, ei1, h2a);
  radial(sm + A_M10, h1p, ei0, ei1, h2b);

  const float4* f0p = reinterpret_cast<const float4*>(p.feat0 + (size_t)s*16);
  float f0[16];
#pragma unroll
  for (int q = 0; q < 4; q++) {
    float4 x = f0p[q];
    f0[q*4] = x.x; f0[q*4+1] = x.y; f0[q*4+2] = x.z; f0[q*4+3] = x.w;
  }
  float bv = p.b00[e];
  float g0 = p.b10[e*3], g1 = p.b10[e*3+1], g2 = p.b10[e*3+2];
  const float4* f1p = reinterpret_cast<const float4*>(p.feat1 + (size_t)s*48);
  float t1[16];
#pragma unroll
  for (int kb = 0; kb < 4; kb++) {
    float4 x0 = f1p[kb*3], x1 = f1p[kb*3+1], x2 = f1p[kb*3+2];
    t1[kb*4]   = x0.x*g0 + x0.y*g1 + x0.z*g2;
    t1[kb*4+1] = x0.w*g0 + x1.x*g1 + x1.y*g2;
    t1[kb*4+2] = x1.z*g0 + x1.w*g1 + x2.x*g2;
    t1[kb*4+3] = x2.y*g0 + x2.z*g1 + x2.w*g2;
  }

  float* outp = p.out + (size_t)d*64;
  const float* w3a = sm + A_W00;
  const float* w3b = sm + A_W10;
#pragma unroll 1
  for (int c = 0; c < 16; c++) {
    float o0 = 0.f;
#pragma unroll
    for (int kb = 0; kb < 4; kb++) {
      float a0=0,a1=0,a2=0,a3=0,u0=0,u1=0,u2=0,u3=0;
      const float* wa = w3a + c*16 + kb*4;
      const float* wb = w3b + c*16 + kb*4;
#pragma unroll
      for (int m = 0; m < 32; m++) {
        float4 va = *reinterpret_cast<const float4*>(wa + m*256);
        float4 vb = *reinterpret_cast<const float4*>(wb + m*256);
        float ha = h2a[m], hb = h2b[m];
        a0=fmaf(ha,va.x,a0); a1=fmaf(ha,va.y,a1); a2=fmaf(ha,va.z,a2); a3=fmaf(ha,va.w,a3);
        u0=fmaf(hb,vb.x,u0); u1=fmaf(hb,vb.y,u1); u2=fmaf(hb,vb.z,u2); u3=fmaf(hb,vb.w,u3);
      }
      float s0 = a0*f0[kb*4] + a1*f0[kb*4+1] + a2*f0[kb*4+2] + a3*f0[kb*4+3];
      float s1 = u0*t1[kb*4] + u1*t1[kb*4+1] + u2*t1[kb*4+2] + u3*t1[kb*4+3];
      o0 += fmaf(bv, s0, s1);
    }
    atomicAdd(outp + c*4, o0);
  }
}

// ---------- kernel B: pairs (0,1)+(1,1) -> out[..,c,1..3] ----------
// smem: w3_01[8192] | w3_11[24576] | mlp01[1152] | mlp11[1152] | h1[256*33] | o1[256*49]
constexpr int B_W01 = 0, B_W11 = 8192, B_M01 = 32768, B_M11 = 33920, B_H1 = 35072;
constexpr int B_O1 = B_H1 + 256*33;          // 43520
constexpr int B_FLOATS = B_O1 + 256*49;      // 56064 f = 224256 B

__global__ void __launch_bounds__(256, 1) convB(P p) {
  extern __shared__ float sm[];
  cpcopy(sm + B_W01, p.w3a, 8192);
  cpcopy(sm + B_W11, p.w3b, 24576);
  cpcopy(sm + B_M01, p.w1a, 64);  cpcopy(sm + B_M01+64,  p.b1a, 32);
  cpcopy(sm + B_M01+96, p.w2a, 1024); cpcopy(sm + B_M01+1120, p.b2a, 32);
  cpcopy(sm + B_M11, p.w1b, 64);  cpcopy(sm + B_M11+64,  p.b1b, 32);
  cpcopy(sm + B_M11+96, p.w2b, 1024); cpcopy(sm + B_M11+1120, p.b2b, 32);
  __syncthreads();

  int e = blockIdx.x * 256 + threadIdx.x;
  if (e >= p.E) return;
  float* h1p = sm + B_H1 + threadIdx.x * 33;
  float* o1p = sm + B_O1 + threadIdx.x * 49;

  int s = p.src[e], d = p.dst[e];
  float ei0 = p.edge_inv[2*e], ei1 = p.edge_inv[2*e+1];
  float h2[32];

  // pair (0,1): out1[c,o] = (rw01[c,:] . f0) * q[o]
  radial(sm + B_M01, h1p, ei0, ei1, h2);
  const float4* f0p = reinterpret_cast<const float4*>(p.feat0 + (size_t)s*16);
  float f0[16];
#pragma unroll
  for (int q = 0; q < 4; q++) {
    float4 x = f0p[q];
    f0[q*4] = x.x; f0[q*4+1] = x.y; f0[q*4+2] = x.z; f0[q*4+3] = x.w;
  }
  float q0 = p.b01[e*3], q1 = p.b01[e*3+1], q2 = p.b01[e*3+2];
  const float* w3c = sm + B_W01;
#pragma unroll 1
  for (int c = 0; c < 16; c++) {
    float v = 0.f;
#pragma unroll
    for (int kb = 0; kb < 4; kb++) {
      float a0=0,a1=0,a2=0,a3=0;
      const float* w = w3c + c*16 + kb*4;
#pragma unroll
      for (int m = 0; m < 32; m++) {
        float4 x = *reinterpret_cast<const float4*>(w + m*256);
        float h = h2[m];
        a0=fmaf(h,x.x,a0); a1=fmaf(h,x.y,a1); a2=fmaf(h,x.z,a2); a3=fmaf(h,x.w,a3);
      }
      v += a0*f0[kb*4] + a1*f0[kb*4+1] + a2*f0[kb*4+2] + a3*f0[kb*4+3];
    }
    o1p[c*3] = v*q0; o1p[c*3+1] = v*q1; o1p[c*3+2] = v*q2;
  }

  // pair (1,1): rw idx = c*48 + ci*3 + f ; basis_11 B[i*9 + f*3 + o]
  radial(sm + B_M11, h1p, ei0, ei1, h2);
  float B27[27];
#pragma unroll
  for (int i = 0; i < 27; i++) B27[i] = p.b11[(size_t)e*27 + i];
  const float* f1b = p.feat1 + (size_t)s*48;
  const float* w3d = sm + B_W11;

#pragma unroll 1
  for (int cinb = 0; cinb < 4; cinb++) {
    const float4* f1p = reinterpret_cast<const float4*>(f1b + cinb*12);
    float4 x0 = f1p[0], x1 = f1p[1], x2 = f1p[2];
    float f1v[12] = {x0.x,x0.y,x0.z,x0.w, x1.x,x1.y,x1.z,x1.w, x2.x,x2.y,x2.z,x2.w};
    float t[36];  // t[cc*9 + f*3 + o] = sum_i f1[ci,i]*B[i,f,o]
#pragma unroll
    for (int cc = 0; cc < 4; cc++)
#pragma unroll
      for (int fo = 0; fo < 9; fo++)
        t[cc*9+fo] = f1v[cc*3]*B27[fo] + f1v[cc*3+1]*B27[9+fo] + f1v[cc*3+2]*B27[18+fo];

#pragma unroll 1
    for (int c = 0; c < 16; c++) {
      float acc[12] = {0,0,0,0,0,0,0,0,0,0,0,0};
      const float* w = w3d + c*48 + cinb*12;
#pragma unroll
      for (int m = 0; m < 32; m++) {
        float4 u0 = *reinterpret_cast<const float4*>(w + m*768);
        float4 u1 = *reinterpret_cast<const float4*>(w + m*768 + 4);
        float4 u2 = *reinterpret_cast<const float4*>(w + m*768 + 8);
        float h = h2[m];
        acc[0]=fmaf(h,u0.x,acc[0]); acc[1]=fmaf(h,u0.y,acc[1]); acc[2]=fmaf(h,u0.z,acc[2]); acc[3]=fmaf(h,u0.w,acc[3]);
        acc[4]=fmaf(h,u1.x,acc[4]); acc[5]=fmaf(h,u1.y,acc[5]); acc[6]=fmaf(h,u1.z,acc[6]); acc[7]=fmaf(h,u1.w,acc[7]);
        acc[8]=fmaf(h,u2.x,acc[8]); acc[9]=fmaf(h,u2.y,acc[9]); acc[10]=fmaf(h,u2.z,acc[10]); acc[11]=fmaf(h,u2.w,acc[11]);
      }
      // acc[cc*3+f] = rw11[c, cinb*4+cc, f]
      float r0 = o1p[c*3], r1 = o1p[c*3+1], r2 = o1p[c*3+2];
#pragma unroll
      for (int cc = 0; cc < 4; cc++)
#pragma unroll
        for (int f = 0; f < 3; f++) {
          float a = acc[cc*3+f];
          r0 = fmaf(a, t[cc*9+f*3],   r0);
          r1 = fmaf(a, t[cc*9+f*3+1], r1);
          r2 = fmaf(a, t[cc*9+f*3+2], r2);
        }
      o1p[c*3] = r0; o1p[c*3+1] = r1; o1p[c*3+2] = r2;
    }
  }

  float* outp = p.out + (size_t)d*64;
#pragma unroll 1
  for (int c = 0; c < 16; c++) {
    atomicAdd(outp + c*4 + 1, o1p[c*3]);
    atomicAdd(outp + c*4 + 2, o1p[c*3+1]);
    atomicAdd(outp + c*4 + 3, o1p[c*3+2]);
  }
}

__global__ void zero_out(float* o, int n) {
  int i = blockIdx.x * blockDim.x + threadIdx.x;
  if (i < n) o[i] = 0.f;
}

}  // namespace

extern "C" void kernel_launch(void* const* d_in, const int* in_sizes, int n_in,
                              void* d_out, int out_size) {
  const float* feat0    = (const float*)d_in[0];
  const float* feat1    = (const float*)d_in[1];
  const float* edge_inv = (const float*)d_in[2];
  const int*   src      = (const int*)d_in[3];
  const int*   dst      = (const int*)d_in[4];
  const float* b00 = (const float*)d_in[5];
  const float* b01 = (const float*)d_in[6];
  const float* b10 = (const float*)d_in[7];
  const float* b11 = (const float*)d_in[8];
  // per-pair MLP blocks: 00 @9, 01 @14, 10 @19, 11 @24
  auto mlp = [&](int base, const float*& w1, const float*& b1, const float*& w2,
                 const float*& b2, const float*& w3) {
    w1 = (const float*)d_in[base];   b1 = (const float*)d_in[base+1];
    w2 = (const float*)d_in[base+2]; b2 = (const float*)d_in[base+3];
    w3 = (const float*)d_in[base+4];
  };
  int E = in_sizes[3];
  float* out = (float*)d_out;

  static bool attr_done = false;
  if (!attr_done) {
    cudaFuncSetAttribute(convA, cudaFuncAttributeMaxDynamicSharedMemorySize, A_FLOATS*4);
    cudaFuncSetAttribute(convB, cudaFuncAttributeMaxDynamicSharedMemorySize, B_FLOATS*4);
    attr_done = true;
  }

  zero_out<<<(out_size + 511)/512, 512>>>(out, out_size);

  P pa{}; pa.feat0 = feat0; pa.feat1 = feat1; pa.edge_inv = edge_inv;
  pa.src = src; pa.dst = dst; pa.b00 = b00; pa.b01 = b01; pa.b10 = b10; pa.b11 = b11;
  pa.out = out; pa.E = E;
  P pb = pa;
  mlp(9,  pa.w1a, pa.b1a, pa.w2a, pa.b2a, pa.w3a);   // 00
  mlp(19, pa.w1b, pa.b1b, pa.w2b, pa.b2b, pa.w3b);   // 10
  mlp(14, pb.w1a, pb.b1a, pb.w2a, pb.b2a, pb.w3a);   // 01
  mlp(24, pb.w1b, pb.b1b, pb.w2b, pb.b2b, pb.w3b);   // 11

  int grid = (E + 255) / 256;
  convA<<<grid, 256, A_FLOATS*4>>>(pa);
  convB<<<grid, 256, B_FLOATS*4>>>(pb);
}

// round 4
// speedup vs baseline: 1.1653x; 1.1653x over previous
#include <cuda_runtime.h>
#include <cuda_bf16.h>

namespace {

using u64 = unsigned long long;

__device__ __forceinline__ u64 pk(float x) {
  u64 d; unsigned xi = __float_as_uint(x);
  asm("mov.b64 %0, {%1, %1};" : "=l"(d) : "r"(xi));
  return d;
}
__device__ __forceinline__ u64 ffma2(u64 a, u64 b, u64 c) {
  u64 d;
  asm("fma.rn.f32x2 %0, %1, %2, %3;" : "=l"(d) : "l"(a), "l"(b), "l"(c));
  return d;
}
__device__ __forceinline__ float2 unpk(u64 d) {
  unsigned lo, hi;
  asm("mov.b64 {%0, %1}, %2;" : "=r"(lo), "=r"(hi) : "l"(d));
  return make_float2(__uint_as_float(lo), __uint_as_float(hi));
}

struct P {
  const float *feat0, *feat1, *edge_inv;
  const int *src, *dst;
  const float *b00, *b01, *b10, *b11;
  const float *w1a, *b1a, *w2a, *b2a, *w3a;   // pair A of the kernel
  const float *w1b, *b1b, *w2b, *b2b, *w3b;   // pair B of the kernel
  float* out;
  int E;
};

__device__ __forceinline__ void cpcopy(float* d, const float* __restrict__ s, int n) {
  for (int i = threadIdx.x; i < n; i += blockDim.x) d[i] = s[i];
}

// h2 = relu(relu(ei@w1+b1)@w2+b2). mlp smem layout: w1[64]|b1[32]|w2[1024]|b2[32]
// h1 lives in registers (fully unrolled); w2 contraction uses packed f32x2.
__device__ __forceinline__ void radial(const float* __restrict__ mlp,
                                       float ei0, float ei1, float h2[32]) {
  const float* w1 = mlp; const float* b1 = mlp + 64;
  const float* w2 = mlp + 96; const float* b2 = mlp + 1120;
  float h1[32];
#pragma unroll
  for (int m = 0; m < 32; m++)
    h1[m] = fmaxf(fmaf(ei0, w1[m], fmaf(ei1, w1[32 + m], b1[m])), 0.f);
  u64 a[16];
#pragma unroll
  for (int j = 0; j < 8; j++) {
    ulonglong2 b = *reinterpret_cast<const ulonglong2*>(b2 + j*4);
    a[j*2] = b.x; a[j*2+1] = b.y;
  }
#pragma unroll
  for (int n = 0; n < 32; n++) {
    u64 h = pk(h1[n]);
    const float* wr = w2 + n*32;
#pragma unroll
    for (int j = 0; j < 8; j++) {
      ulonglong2 w = *reinterpret_cast<const ulonglong2*>(wr + j*4);
      a[j*2]   = ffma2(h, w.x, a[j*2]);
      a[j*2+1] = ffma2(h, w.y, a[j*2+1]);
    }
  }
#pragma unroll
  for (int j = 0; j < 16; j++) {
    float2 p = unpk(a[j]);
    h2[j*2]   = fmaxf(p.x, 0.f);
    h2[j*2+1] = fmaxf(p.y, 0.f);
  }
}

// Contract h2 against one nf=1 w3 block (16x16 per m), dot with vec[16], add to o[16].
// w3 smem layout: [m*256 + c*16 + k].
__device__ __forceinline__ void contract16(const float* __restrict__ w3,
                                           const float h2[32], const float vec[16],
                                           float o[16]) {
#pragma unroll 1
  for (int c = 0; c < 16; c++) {
    u64 A[8];
#pragma unroll
    for (int j = 0; j < 8; j++) A[j] = 0ull;
#pragma unroll
    for (int m = 0; m < 32; m++) {
      u64 h = pk(h2[m]);
      const float* wr = w3 + c*16 + m*256;
#pragma unroll
      for (int kb = 0; kb < 4; kb++) {
        ulonglong2 w = *reinterpret_cast<const ulonglong2*>(wr + kb*4);
        A[kb*2]   = ffma2(h, w.x, A[kb*2]);
        A[kb*2+1] = ffma2(h, w.y, A[kb*2+1]);
      }
    }
    float v = 0.f;
#pragma unroll
    for (int kb = 0; kb < 4; kb++) {
      float2 x = unpk(A[kb*2]);
      float2 y = unpk(A[kb*2+1]);
      v += x.x*vec[kb*4] + x.y*vec[kb*4+1] + y.x*vec[kb*4+2] + y.y*vec[kb*4+3];
    }
    o[c] += v;
  }
}

// ---------- kernel A: pairs (0,0)+(1,0) -> out[..,c,0] ----------
// smem: w3_00[8192] | w3_10[8192] | mlp00[1152] | mlp10[1152]
constexpr int A_W00 = 0, A_W10 = 8192, A_M00 = 16384, A_M10 = 17536;
constexpr int A_FLOATS = 18688;   // 74752 B

__global__ void __launch_bounds__(256, 2) convA(P p) {
  extern __shared__ float sm[];
  cpcopy(sm + A_W00, p.w3a, 8192);
  cpcopy(sm + A_W10, p.w3b, 8192);
  cpcopy(sm + A_M00, p.w1a, 64);  cpcopy(sm + A_M00+64,  p.b1a, 32);
  cpcopy(sm + A_M00+96, p.w2a, 1024); cpcopy(sm + A_M00+1120, p.b2a, 32);
  cpcopy(sm + A_M10, p.w1b, 64);  cpcopy(sm + A_M10+64,  p.b1b, 32);
  cpcopy(sm + A_M10+96, p.w2b, 1024); cpcopy(sm + A_M10+1120, p.b2b, 32);
  __syncthreads();

  int e = blockIdx.x * 256 + threadIdx.x;
  if (e >= p.E) return;

  int s = p.src[e], d = p.dst[e];
  float ei0 = p.edge_inv[2*e], ei1 = p.edge_inv[2*e+1];

  float o0[16];
#pragma unroll
  for (int c = 0; c < 16; c++) o0[c] = 0.f;

  // ---- phase (0,0): fold b00 into h2 ----
  {
    float h2[32];
    radial(sm + A_M00, ei0, ei1, h2);
    float bv = p.b00[e];
#pragma unroll
    for (int m = 0; m < 32; m++) h2[m] *= bv;
    float f0[16];
    const float4* f0p = reinterpret_cast<const float4*>(p.feat0 + (size_t)s*16);
#pragma unroll
    for (int q = 0; q < 4; q++) {
      float4 x = f0p[q];
      f0[q*4] = x.x; f0[q*4+1] = x.y; f0[q*4+2] = x.z; f0[q*4+3] = x.w;
    }
    contract16(sm + A_W00, h2, f0, o0);
  }

  // ---- phase (1,0): t1[k] = sum_i feat1[s,k,i]*basis10[e,i] ----
  {
    float h2[32];
    radial(sm + A_M10, ei0, ei1, h2);
    float g0 = p.b10[e*3], g1 = p.b10[e*3+1], g2 = p.b10[e*3+2];
    const float4* f1p = reinterpret_cast<const float4*>(p.feat1 + (size_t)s*48);
    float t1[16];
#pragma unroll
    for (int kb = 0; kb < 4; kb++) {
      float4 x0 = f1p[kb*3], x1 = f1p[kb*3+1], x2 = f1p[kb*3+2];
      t1[kb*4]   = x0.x*g0 + x0.y*g1 + x0.z*g2;
      t1[kb*4+1] = x0.w*g0 + x1.x*g1 + x1.y*g2;
      t1[kb*4+2] = x1.z*g0 + x1.w*g1 + x2.x*g2;
      t1[kb*4+3] = x2.y*g0 + x2.z*g1 + x2.w*g2;
    }
    contract16(sm + A_W10, h2, t1, o0);
  }

  float* outp = p.out + (size_t)d*64;
#pragma unroll 1
  for (int c = 0; c < 16; c++) atomicAdd(outp + c*4, o0[c]);
}

// ---------- kernel B: pairs (0,1)+(1,1) -> out[..,c,1..3] ----------
// smem: w3_01[8192] | w3_11[24576] | mlp01[1152] | mlp11[1152] | o1[256*49]
constexpr int B_W01 = 0, B_W11 = 8192, B_M01 = 32768, B_M11 = 33920, B_O1 = 35072;
constexpr int B_FLOATS = B_O1 + 256*49;   // 47616 f = 190464 B

__global__ void __launch_bounds__(256, 1) convB(P p) {
  extern __shared__ float sm[];
  cpcopy(sm + B_W01, p.w3a, 8192);
  cpcopy(sm + B_W11, p.w3b, 24576);
  cpcopy(sm + B_M01, p.w1a, 64);  cpcopy(sm + B_M01+64,  p.b1a, 32);
  cpcopy(sm + B_M01+96, p.w2a, 1024); cpcopy(sm + B_M01+1120, p.b2a, 32);
  cpcopy(sm + B_M11, p.w1b, 64);  cpcopy(sm + B_M11+64,  p.b1b, 32);
  cpcopy(sm + B_M11+96, p.w2b, 1024); cpcopy(sm + B_M11+1120, p.b2b, 32);
  __syncthreads();

  int e = blockIdx.x * 256 + threadIdx.x;
  if (e >= p.E) return;
  float* o1p = sm + B_O1 + threadIdx.x * 49;

  int s = p.src[e], d = p.dst[e];
  float ei0 = p.edge_inv[2*e], ei1 = p.edge_inv[2*e+1];

  // ---- pair (0,1): out1[c,o] = (rw01[c,:] . f0) * q[o] ----
  {
    float h2[32];
    radial(sm + B_M01, ei0, ei1, h2);
    float f0[16];
    const float4* f0p = reinterpret_cast<const float4*>(p.feat0 + (size_t)s*16);
#pragma unroll
    for (int q = 0; q < 4; q++) {
      float4 x = f0p[q];
      f0[q*4] = x.x; f0[q*4+1] = x.y; f0[q*4+2] = x.z; f0[q*4+3] = x.w;
    }
    float v01[16];
#pragma unroll
    for (int c = 0; c < 16; c++) v01[c] = 0.f;
    contract16(sm + B_W01, h2, f0, v01);
    float q0 = p.b01[e*3], q1 = p.b01[e*3+1], q2 = p.b01[e*3+2];
#pragma unroll 1
    for (int c = 0; c < 16; c++) {
      o1p[c*3]   = v01[c]*q0;
      o1p[c*3+1] = v01[c]*q1;
      o1p[c*3+2] = v01[c]*q2;
    }
  }

  // ---- pair (1,1): rw idx = c*48 + k*3 + f ; basis_11 B[i*9 + f*3 + o] ----
  {
    float h2[32];
    radial(sm + B_M11, ei0, ei1, h2);
    float B27[27];
#pragma unroll
    for (int i = 0; i < 27; i++) B27[i] = p.b11[(size_t)e*27 + i];
    const float* f1b = p.feat1 + (size_t)s*48;
    const float* w3d = sm + B_W11;

#pragma unroll 1
    for (int cinb = 0; cinb < 4; cinb++) {
      const float4* f1p = reinterpret_cast<const float4*>(f1b + cinb*12);
      float4 x0 = f1p[0], x1 = f1p[1], x2 = f1p[2];
      float f1v[12] = {x0.x,x0.y,x0.z,x0.w, x1.x,x1.y,x1.z,x1.w, x2.x,x2.y,x2.z,x2.w};
      float t[36];  // t[cc*9 + f*3 + o] = sum_i f1[ci,i]*B[i,f,o]
#pragma unroll
      for (int cc = 0; cc < 4; cc++)
#pragma unroll
        for (int fo = 0; fo < 9; fo++)
          t[cc*9+fo] = f1v[cc*3]*B27[fo] + f1v[cc*3+1]*B27[9+fo] + f1v[cc*3+2]*B27[18+fo];

#pragma unroll 1
      for (int c = 0; c < 16; c++) {
        u64 acc[6];
#pragma unroll
        for (int j = 0; j < 6; j++) acc[j] = 0ull;
        const float* w = w3d + c*48 + cinb*12;
#pragma unroll
        for (int m = 0; m < 32; m++) {
          u64 h = pk(h2[m]);
          const float* wr = w + m*768;
          ulonglong2 W0 = *reinterpret_cast<const ulonglong2*>(wr);
          ulonglong2 W1 = *reinterpret_cast<const ulonglong2*>(wr + 4);
          ulonglong2 W2 = *reinterpret_cast<const ulonglong2*>(wr + 8);
          acc[0] = ffma2(h, W0.x, acc[0]); acc[1] = ffma2(h, W0.y, acc[1]);
          acc[2] = ffma2(h, W1.x, acc[2]); acc[3] = ffma2(h, W1.y, acc[3]);
          acc[4] = ffma2(h, W2.x, acc[4]); acc[5] = ffma2(h, W2.y, acc[5]);
        }
        float a[12];
#pragma unroll
        for (int j = 0; j < 6; j++) {
          float2 pr = unpk(acc[j]);
          a[j*2] = pr.x; a[j*2+1] = pr.y;
        }
        // a[cc*3+f] = rw11[c, cinb*4+cc, f]
        float r0 = o1p[c*3], r1 = o1p[c*3+1], r2 = o1p[c*3+2];
#pragma unroll
        for (int cc = 0; cc < 4; cc++)
#pragma unroll
          for (int f = 0; f < 3; f++) {
            float av = a[cc*3+f];
            r0 = fmaf(av, t[cc*9+f*3],   r0);
            r1 = fmaf(av, t[cc*9+f*3+1], r1);
            r2 = fmaf(av, t[cc*9+f*3+2], r2);
          }
        o1p[c*3] = r0; o1p[c*3+1] = r1; o1p[c*3+2] = r2;
      }
    }
  }

  float* outp = p.out + (size_t)d*64;
#pragma unroll 1
  for (int c = 0; c < 16; c++) {
    atomicAdd(outp + c*4 + 1, o1p[c*3]);
    atomicAdd(outp + c*4 + 2, o1p[c*3+1]);
    atomicAdd(outp + c*4 + 3, o1p[c*3+2]);
  }
}

__global__ void zero_out(float* o, int n) {
  int i = blockIdx.x * blockDim.x + threadIdx.x;
  if (i < n) o[i] = 0.f;
}

}  // namespace

extern "C" void kernel_launch(void* const* d_in, const int* in_sizes, int n_in,
                              void* d_out, int out_size) {
  const float* feat0    = (const float*)d_in[0];
  const float* feat1    = (const float*)d_in[1];
  const float* edge_inv = (const float*)d_in[2];
  const int*   src      = (const int*)d_in[3];
  const int*   dst      = (const int*)d_in[4];
  const float* b00 = (const float*)d_in[5];
  const float* b01 = (const float*)d_in[6];
  const float* b10 = (const float*)d_in[7];
  const float* b11 = (const float*)d_in[8];
  auto mlp = [&](int base, const float*& w1, const float*& b1, const float*& w2,
                 const float*& b2, const float*& w3) {
    w1 = (const float*)d_in[base];   b1 = (const float*)d_in[base+1];
    w2 = (const float*)d_in[base+2]; b2 = (const float*)d_in[base+3];
    w3 = (const float*)d_in[base+4];
  };
  int E = in_sizes[3];
  float* out = (float*)d_out;

  static bool attr_done = false;
  if (!attr_done) {
    cudaFuncSetAttribute(convA, cudaFuncAttributeMaxDynamicSharedMemorySize, A_FLOATS*4);
    cudaFuncSetAttribute(convB, cudaFuncAttributeMaxDynamicSharedMemorySize, B_FLOATS*4);
    attr_done = true;
  }

  zero_out<<<(out_size + 511)/512, 512>>>(out, out_size);

  P pa{}; pa.feat0 = feat0; pa.feat1 = feat1; pa.edge_inv = edge_inv;
  pa.src = src; pa.dst = dst; pa.b00 = b00; pa.b01 = b01; pa.b10 = b10; pa.b11 = b11;
  pa.out = out; pa.E = E;
  P pb = pa;
  mlp(9,  pa.w1a, pa.b1a, pa.w2a, pa.b2a, pa.w3a);   // 00
  mlp(19, pa.w1b, pa.b1b, pa.w2b, pa.b2b, pa.w3b);   // 10
  mlp(14, pb.w1a, pb.b1a, pb.w2a, pb.b2a, pb.w3a);   // 01
  mlp(24, pb.w1b, pb.b1b, pb.w2b, pb.b2b, pb.w3b);   // 11

  int grid = (E + 255) / 256;
  convA<<<grid, 256, A_FLOATS*4>>>(pa);
  convB<<<grid, 256, B_FLOATS*4>>>(pb);
}